// round 8
// baseline (speedup 1.0000x reference)
#include <cuda_runtime.h>
#include <cuda_bf16.h>

#define N_TOTAL 16384
#define M_ROWS  4096
#define DIM     256
#define GRID    512      // one full-occupancy wave: 4 blocks/SM x 148 SMs = 592 >= 512
#define NTHR    512

// Scratch (no allocation allowed)
__device__ float g_part [GRID * DIM];   // phase-A per-block column partials
__device__ float g_part2[32 * DIM];     // phase-B partials
__device__ float g_ksum[DIM];
__device__ float g_v[DIM];
__device__ float g_c;

// Grid barrier state (zero-initialized at module load; generation counters
// survive graph replays — counter is reset to 0 by the releaser each use).
__device__ unsigned           g_cnt[4];
__device__ volatile unsigned  g_gen[4];

// ---------------------------------------------------------------------------
// Sense-reversal grid barrier. Safe because the entire grid is co-resident
// (single wave, guaranteed by __launch_bounds__(512,4) and GRID=512<=592).
// Generation is read BEFORE arrival so a late reader can never miss the
// release. threadfence before/after gives device-scope visibility of the
// phase's global writes (classic threadfence-reduction pattern).
// ---------------------------------------------------------------------------
__device__ __forceinline__ void grid_barrier(int slot) {
    __threadfence();
    __syncthreads();
    if (threadIdx.x == 0) {
        const unsigned gen = g_gen[slot];          // read before arrive!
        const unsigned tk  = atomicAdd(&g_cnt[slot], 1u);
        if (tk == GRID - 1) {
            g_cnt[slot] = 0;                       // reset for next replay
            __threadfence();
            g_gen[slot] = gen + 1;                 // release
        } else {
            while (g_gen[slot] == gen) { __nanosleep(64); }
        }
    }
    __syncthreads();
    __threadfence();
}

// ---------------------------------------------------------------------------
// One fused persistent kernel, 5 phases, 4 grid barriers, 1 launch.
// ---------------------------------------------------------------------------
__global__ void __launch_bounds__(NTHR, 4)
fused_kernel(const float* __restrict__ mashup,
             const float* __restrict__ api,
             const float* __restrict__ new_api,
             const float* __restrict__ q_w,
             const float* __restrict__ q_b,
             const float* __restrict__ k_w,
             const float* __restrict__ k_b,
             float* __restrict__ out) {
    __shared__ float4 sm4[NTHR];          // 8 KB, reused across phases
    __shared__ float  s_sh[DIM];
    __shared__ float  sc;
    float* smf = reinterpret_cast<float*>(sm4);

    const int t   = threadIdx.x;
    const int bid = blockIdx.x;
    const int c4  = t & 63;               // float4 column
    const int sub = t >> 6;               // 0..7

    // ---- Phase A: column partial sums of [mashup ; new_api] ---------------
    // r = bid + 512*(sub + 8*m), m=0..3 -> exactly covers 0..16383, 4
    // independent coalesced float4 loads per thread, no predication.
    {
        float4 acc = make_float4(0.f, 0.f, 0.f, 0.f);
        #pragma unroll
        for (int m = 0; m < 4; ++m) {
            const int r = bid + GRID * (sub + 8 * m);
            const float* src = (r < M_ROWS)
                ? (mashup + (size_t)r * DIM)
                : (new_api + (size_t)(r - M_ROWS) * DIM);
            const float4 x = reinterpret_cast<const float4*>(src)[c4];
            acc.x += x.x; acc.y += x.y; acc.z += x.z; acc.w += x.w;
        }
        sm4[t] = acc;
        __syncthreads();
        if (t < 64) {
            float4 r = sm4[t];
            #pragma unroll
            for (int s = 1; s < 8; ++s) {
                const float4 a = sm4[t + 64 * s];
                r.x += a.x; r.y += a.y; r.z += a.z; r.w += a.w;
            }
            reinterpret_cast<float4*>(g_part + (size_t)bid * DIM)[t] = r;
        }
    }
    grid_barrier(0);

    // ---- Phase B: collapse 512 partials -> 32 (blocks 0..31) --------------
    if (bid < 32) {
        float4 acc = make_float4(0.f, 0.f, 0.f, 0.f);
        #pragma unroll
        for (int m = 0; m < 2; ++m) {
            const int p = bid + 32 * (sub + 8 * m);       // 16 rows/block
            const float4 x = reinterpret_cast<const float4*>(
                g_part + (size_t)p * DIM)[c4];
            acc.x += x.x; acc.y += x.y; acc.z += x.z; acc.w += x.w;
        }
        sm4[t] = acc;
        __syncthreads();
        if (t < 64) {
            float4 r = sm4[t];
            #pragma unroll
            for (int s = 1; s < 8; ++s) {
                const float4 a = sm4[t + 64 * s];
                r.x += a.x; r.y += a.y; r.z += a.z; r.w += a.w;
            }
            reinterpret_cast<float4*>(g_part2 + (size_t)bid * DIM)[t] = r;
        }
    }
    grid_barrier(1);

    // ---- Phase C: ksum[j] = sum_i s[i]*k_w[i][j] + N*k_b[j] (blocks 0..63)
    if (bid < 64) {
        // reduce the 32 stage-2 partials into s_sh[256]
        float4 acc = make_float4(0.f, 0.f, 0.f, 0.f);
        #pragma unroll
        for (int m = 0; m < 4; ++m) {
            const int p = sub + 8 * m;                    // 0..31
            const float4 x = reinterpret_cast<const float4*>(
                g_part2 + (size_t)p * DIM)[c4];
            acc.x += x.x; acc.y += x.y; acc.z += x.z; acc.w += x.w;
        }
        sm4[t] = acc;
        __syncthreads();
        if (t < 64) {
            float4 r = sm4[t];
            #pragma unroll
            for (int s = 1; s < 8; ++s) {
                const float4 a = sm4[t + 64 * s];
                r.x += a.x; r.y += a.y; r.z += a.z; r.w += a.w;
            }
            reinterpret_cast<float4*>(s_sh)[t] = r;
        }
        __syncthreads();

        // this block's 4 columns
        const int jb = bid * 4;
        if (t < 256) {
            const float si = s_sh[t];
            const float4 w = reinterpret_cast<const float4*>(
                k_w + (size_t)t * DIM + jb)[0];
            sm4[t] = make_float4(si * w.x, si * w.y, si * w.z, si * w.w);
        }
        __syncthreads();
        #pragma unroll
        for (int off = 128; off >= 1; off >>= 1) {
            if (t < off) {
                const float4 a = sm4[t], b = sm4[t + off];
                sm4[t] = make_float4(a.x + b.x, a.y + b.y,
                                     a.z + b.z, a.w + b.w);
            }
            __syncthreads();
        }
        if (t == 0) {
            const float4 kb = reinterpret_cast<const float4*>(k_b + jb)[0];
            float4 r = sm4[0];
            r.x += (float)N_TOTAL * kb.x;
            r.y += (float)N_TOTAL * kb.y;
            r.z += (float)N_TOTAL * kb.z;
            r.w += (float)N_TOTAL * kb.w;
            reinterpret_cast<float4*>(g_ksum + jb)[0] = r;
        }
    }
    grid_barrier(2);

    // ---- Phase D: v = q_w @ ksum (blocks 0..31, 8 rows each); c (block 32)
    if (bid < 32) {
        const int row = bid * 8 + sub;                    // 0..255
        const float4 a = reinterpret_cast<const float4*>(
            q_w + (size_t)row * DIM)[c4];
        const float4 k = reinterpret_cast<const float4*>(g_ksum)[c4];
        smf[t] = a.x * k.x + a.y * k.y + a.z * k.z + a.w * k.w;
        __syncthreads();
        #pragma unroll
        for (int off = 32; off >= 1; off >>= 1) {
            if ((t & 63) < off) smf[t] += smf[t + off];
            __syncthreads();
        }
        if ((t & 63) == 0) g_v[row] = smf[t];
    } else if (bid == 32) {
        smf[t] = (t < 256) ? (q_b[t] * g_ksum[t]) : 0.f;
        __syncthreads();
        #pragma unroll
        for (int off = 128; off >= 1; off >>= 1) {
            if (t < off) smf[t] += smf[t + off];
            __syncthreads();
        }
        if (t == 0) g_c = smf[0];
    }
    grid_barrier(3);

    // ---- Phase E: out[i] = (combine[i].v + c)/16, combine = [mashup ; api]
    // 16 warps/block, 2 rows/warp -> 32 rows/block x 512 = 16384. Rows of a
    // warp never straddle the 4096 boundary (row0 even).
    {
        if (t < DIM) s_sh[t] = g_v[t];
        if (t == 0)  sc = g_c;
        __syncthreads();

        const int warp = t >> 5, lane = t & 31;
        const int row0 = (bid * 16 + warp) * 2;

        const float* src;
        int base;
        if (row0 < M_ROWS) { src = mashup; base = row0; }
        else               { src = api;    base = row0 - M_ROWS; }

        const float4* vp = reinterpret_cast<const float4*>(s_sh);
        const float4 v0 = vp[lane], v1 = vp[lane + 32];

        const float4* p0 = reinterpret_cast<const float4*>(src + (size_t)base * DIM);
        const float4* p1 = reinterpret_cast<const float4*>(src + (size_t)(base + 1) * DIM);
        const float4 a0 = p0[lane], a1 = p0[lane + 32];
        const float4 b0 = p1[lane], b1 = p1[lane + 32];

        float accA = a0.x * v0.x + a0.y * v0.y + a0.z * v0.z + a0.w * v0.w
                   + a1.x * v1.x + a1.y * v1.y + a1.z * v1.z + a1.w * v1.w;
        float accB = b0.x * v0.x + b0.y * v0.y + b0.z * v0.z + b0.w * v0.w
                   + b1.x * v1.x + b1.y * v1.y + b1.z * v1.z + b1.w * v1.w;

        #pragma unroll
        for (int off = 16; off > 0; off >>= 1) {
            accA += __shfl_xor_sync(0xFFFFFFFFu, accA, off);
            accB += __shfl_xor_sync(0xFFFFFFFFu, accB, off);
        }
        if (lane == 0) {
            out[row0]     = (accA + sc) * 0.0625f;        // 1/sqrt(256)
            out[row0 + 1] = (accB + sc) * 0.0625f;
        }
    }
}

// ---------------------------------------------------------------------------
// Launch. Inputs (metadata order): mashup, api, new_api, q_w, q_b, k_w, k_b,
// embedding_dim (fixed 256, unused). ONE launch, zero inter-kernel overhead.
// ---------------------------------------------------------------------------
extern "C" void kernel_launch(void* const* d_in, const int* in_sizes, int n_in,
                              void* d_out, int out_size) {
    const float* mashup  = (const float*)d_in[0];
    const float* api     = (const float*)d_in[1];
    const float* new_api = (const float*)d_in[2];
    const float* q_w     = (const float*)d_in[3];
    const float* q_b     = (const float*)d_in[4];
    const float* k_w     = (const float*)d_in[5];
    const float* k_b     = (const float*)d_in[6];
    float* out = (float*)d_out;

    fused_kernel<<<GRID, NTHR>>>(mashup, api, new_api,
                                 q_w, q_b, k_w, k_b, out);
}

// round 10
// speedup vs baseline: 1.3509x; 1.3509x over previous
#include <cuda_runtime.h>
#include <cuda_bf16.h>

#define N_TOTAL 16384
#define M_ROWS  4096
#define DIM     256
#define GRID    512          // both kernels: one wave at 4 blocks/SM (592 slots)
#define NTHR    512
#define PAD     32           // 128B stride between atomic targets (own L2 line)

// Scratch (no allocation allowed). All zero at module load.
__device__ float    g_s [DIM * PAD];   // column sums (padded); zeroed by k2 last block
__device__ float    g_vp[DIM * PAD];   // v (padded);           zeroed by k1 block 0
__device__ float    g_c;               //                        zeroed by k1 block 0
__device__ unsigned g_vdone;           // 64-arrival flag;       zeroed by k1 block 0
__device__ unsigned g_done;            // k2 completion ticket;  self-resetting

// ---------------------------------------------------------------------------
// k1: column sums of combine_new = [mashup ; new_api] via padded atomics.
// 512 blocks x 512 thr, 4 independent coalesced float4 loads per thread,
// exact row cover, no predication. Block-level smem tree -> 64 threads hold
// float4 column totals -> 256 RED.ADD per block to 128B-strided addresses
// (spread across LTS slices; ~512 atomics/address total, fully hidden under
// the 16.8MB DRAM stream). Block 0 also zeroes the k2-phase accumulators.
// ---------------------------------------------------------------------------
__global__ void __launch_bounds__(NTHR, 4)
colsum_kernel(const float* __restrict__ mashup,
              const float* __restrict__ new_api) {
    const int t   = threadIdx.x;
    const int c4  = t & 63;
    const int sub = t >> 6;                  // 0..7
    const int bid = blockIdx.x;

    if (bid == 0) {                          // zero next-phase state
        #pragma unroll
        for (int m = 0; m < 16; ++m) g_vp[t + NTHR * m] = 0.f;
        if (t == 0) { g_c = 0.f; g_vdone = 0u; }
    }

    float4 acc = make_float4(0.f, 0.f, 0.f, 0.f);
    #pragma unroll
    for (int m = 0; m < 4; ++m) {
        const int r = bid + GRID * (sub + 8 * m);        // covers 0..16383
        const float* src = (r < M_ROWS)
            ? (mashup + (size_t)r * DIM)
            : (new_api + (size_t)(r - M_ROWS) * DIM);
        const float4 x = reinterpret_cast<const float4*>(src)[c4];
        acc.x += x.x; acc.y += x.y; acc.z += x.z; acc.w += x.w;
    }

    __shared__ float4 sm4[NTHR];
    sm4[t] = acc;
    __syncthreads();
    if (t < 64) {
        float4 r = sm4[t];
        #pragma unroll
        for (int s = 1; s < 8; ++s) {
            const float4 a = sm4[t + 64 * s];
            r.x += a.x; r.y += a.y; r.z += a.z; r.w += a.w;
        }
        // columns 4t..4t+3, each on its own 128B line
        atomicAdd(&g_s[(4 * t + 0) * PAD], r.x);
        atomicAdd(&g_s[(4 * t + 1) * PAD], r.y);
        atomicAdd(&g_s[(4 * t + 2) * PAD], r.z);
        atomicAdd(&g_s[(4 * t + 3) * PAD], r.w);
    }
}

// ---------------------------------------------------------------------------
// k2: fused middle + final. 512 blocks x 512 thr, single co-resident wave.
//  * blocks 0..63 (workers): ksum cols 4b..4b+3 = k_w^T s + N k_b (local),
//    scatter v += q_w[:,cols]*ksum_cols and c += q_b[cols].ksum_cols via
//    padded atomics, fence, then bump g_vdone. Workers never wait.
//  * ALL blocks issue their 4 row float4 loads BEFORE the spin, so the DRAM
//    stream overlaps the worker phase. Then spin on g_vdone==64 (release by
//    workers / acquire fence by readers), pull v/c from L2, dot, reduce,
//    store. Co-residency (4 blocks/SM cap, 592 slots >= 512) guarantees the
//    workers run => no deadlock.
//  * Last-finished block (ticket) zeroes g_s for the next graph replay.
// ---------------------------------------------------------------------------
__global__ void __launch_bounds__(NTHR, 4)
fused_final(const float* __restrict__ mashup,
            const float* __restrict__ api,
            const float* __restrict__ q_w,
            const float* __restrict__ q_b,
            const float* __restrict__ k_w,
            const float* __restrict__ k_b,
            float* __restrict__ out) {
    __shared__ float4 sm4[256];
    __shared__ float  vs[DIM];
    __shared__ float  sc;
    __shared__ unsigned s_last;

    const int t   = threadIdx.x;
    const int bid = blockIdx.x;

    // ---- worker phase (blocks 0..63) --------------------------------------
    if (bid < 64) {
        const int jb = bid * 4;
        if (t < 256) {
            const float  si = __ldcg(&g_s[t * PAD]);
            const float4 kw = *reinterpret_cast<const float4*>(
                k_w + (size_t)t * DIM + jb);
            sm4[t] = make_float4(si * kw.x, si * kw.y, si * kw.z, si * kw.w);
        }
        __syncthreads();
        #pragma unroll
        for (int off = 128; off >= 1; off >>= 1) {
            if (t < off) {
                const float4 a = sm4[t], b = sm4[t + off];
                sm4[t] = make_float4(a.x + b.x, a.y + b.y,
                                     a.z + b.z, a.w + b.w);
            }
            __syncthreads();
        }
        if (t == 0) {
            const float4 kb = *reinterpret_cast<const float4*>(k_b + jb);
            float4 ks = sm4[0];
            ks.x += (float)N_TOTAL * kb.x;
            ks.y += (float)N_TOTAL * kb.y;
            ks.z += (float)N_TOTAL * kb.z;
            ks.w += (float)N_TOTAL * kb.w;
            sm4[0] = ks;
            const float4 qb = *reinterpret_cast<const float4*>(q_b + jb);
            atomicAdd(&g_c, qb.x * ks.x + qb.y * ks.y
                          + qb.z * ks.z + qb.w * ks.w);
        }
        __syncthreads();
        const float4 ks = sm4[0];
        if (t < 256) {
            const float4 qw = *reinterpret_cast<const float4*>(
                q_w + (size_t)t * DIM + jb);
            atomicAdd(&g_vp[t * PAD],
                      qw.x * ks.x + qw.y * ks.y + qw.z * ks.z + qw.w * ks.w);
        }
        __threadfence();                      // release: v/c visible before flag
        __syncthreads();
        if (t == 0) atomicAdd(&g_vdone, 1u);
    }

    // ---- issue row loads (all blocks) -------------------------------------
    const int warp = t >> 5, lane = t & 31;
    const int row0 = (bid * 16 + warp) * 2;      // 2 rows/warp, never straddles
    const float* src;
    int base;
    if (row0 < M_ROWS) { src = mashup; base = row0; }
    else               { src = api;    base = row0 - M_ROWS; }

    const float4* p0 = reinterpret_cast<const float4*>(src + (size_t)base * DIM);
    const float4* p1 = reinterpret_cast<const float4*>(src + (size_t)(base + 1) * DIM);
    const float4 a0 = p0[lane], a1 = p0[lane + 32];
    const float4 b0 = p1[lane], b1 = p1[lane + 32];

    // ---- wait for v (cheap 64-arrival flag) -------------------------------
    if (t == 0) {
        while (*(volatile unsigned*)&g_vdone < 64u) { __nanosleep(32); }
        __threadfence();                      // acquire: order flag -> v/c reads
    }
    __syncthreads();
    if (t < DIM) vs[t] = __ldcg(&g_vp[t * PAD]);
    if (t == 0)  sc    = __ldcg(&g_c);
    __syncthreads();

    // ---- final dot + reduce + store ---------------------------------------
    const float4* vp = reinterpret_cast<const float4*>(vs);
    const float4 v0 = vp[lane], v1 = vp[lane + 32];

    float accA = a0.x * v0.x + a0.y * v0.y + a0.z * v0.z + a0.w * v0.w
               + a1.x * v1.x + a1.y * v1.y + a1.z * v1.z + a1.w * v1.w;
    float accB = b0.x * v0.x + b0.y * v0.y + b0.z * v0.z + b0.w * v0.w
               + b1.x * v1.x + b1.y * v1.y + b1.z * v1.z + b1.w * v1.w;

    #pragma unroll
    for (int off = 16; off > 0; off >>= 1) {
        accA += __shfl_xor_sync(0xFFFFFFFFu, accA, off);
        accB += __shfl_xor_sync(0xFFFFFFFFu, accB, off);
    }
    if (lane == 0) {
        out[row0]     = (accA + sc) * 0.0625f;   // 1/sqrt(256)
        out[row0 + 1] = (accB + sc) * 0.0625f;
    }

    // ---- last block zeroes g_s for the next replay ------------------------
    __syncthreads();
    if (t == 0) {
        __threadfence();
        const unsigned tk = atomicAdd(&g_done, 1u);
        s_last = (tk == GRID - 1) ? 1u : 0u;
    }
    __syncthreads();
    if (s_last) {
        #pragma unroll
        for (int m = 0; m < 16; ++m) g_s[t + NTHR * m] = 0.f;
        if (t == 0) g_done = 0u;
    }
}

// ---------------------------------------------------------------------------
// Launch. Inputs (metadata order): mashup, api, new_api, q_w, q_b, k_w, k_b,
// embedding_dim (fixed 256, unused). TWO launches, no grid-wide barriers.
// ---------------------------------------------------------------------------
extern "C" void kernel_launch(void* const* d_in, const int* in_sizes, int n_in,
                              void* d_out, int out_size) {
    const float* mashup  = (const float*)d_in[0];
    const float* api     = (const float*)d_in[1];
    const float* new_api = (const float*)d_in[2];
    const float* q_w     = (const float*)d_in[3];
    const float* q_b     = (const float*)d_in[4];
    const float* k_w     = (const float*)d_in[5];
    const float* k_b     = (const float*)d_in[6];
    float* out = (float*)d_out;

    colsum_kernel<<<GRID, NTHR>>>(mashup, new_api);
    fused_final  <<<GRID, NTHR>>>(mashup, api, q_w, q_b, k_w, k_b, out);
}

// round 12
// speedup vs baseline: 1.5434x; 1.1425x over previous
#include <cuda_runtime.h>
#include <cuda_bf16.h>

#define N_TOTAL 16384
#define M_ROWS  4096
#define DIM     256
#define GRID    512          // streaming kernels: one wave at 4 blocks/SM
#define NTHR    512
#define PAD     32           // 128B stride between atomic targets (own L2 line)

// Scratch (no allocation; zero at module load; self-rezeroing across replays)
__device__ float g_s [DIM * PAD];   // column sums (padded); zeroed by k3 block 0
__device__ float g_vp[DIM * PAD];   // v (padded atomic accum); zeroed by k1 block 0
__device__ float g_c;               // scalar; zeroed by k1 block 0

// ---------------------------------------------------------------------------
// k1: column sums of combine_new = [mashup ; new_api].
// 512 x 512, 4 independent coalesced float4 loads/thread, exact row cover.
// Block tree-reduce -> 256 RED.ADD to 128B-strided g_s lines.
// Measured at ~5.4 TB/s in this exact shape (R10). Block 0 zeroes k2 state.
// ---------------------------------------------------------------------------
__global__ void __launch_bounds__(NTHR, 4)
colsum_kernel(const float* __restrict__ mashup,
              const float* __restrict__ new_api) {
    const int t   = threadIdx.x;
    const int c4  = t & 63;
    const int sub = t >> 6;                  // 0..7
    const int bid = blockIdx.x;

    if (bid == 0) {                          // zero k2 accumulators (unused here)
        #pragma unroll
        for (int m = 0; m < 16; ++m) g_vp[t + NTHR * m] = 0.f;
        if (t == 0) g_c = 0.f;
    }

    float4 acc = make_float4(0.f, 0.f, 0.f, 0.f);
    #pragma unroll
    for (int m = 0; m < 4; ++m) {
        const int r = bid + GRID * (sub + 8 * m);        // covers 0..16383
        const float* src = (r < M_ROWS)
            ? (mashup + (size_t)r * DIM)
            : (new_api + (size_t)(r - M_ROWS) * DIM);
        const float4 x = reinterpret_cast<const float4*>(src)[c4];
        acc.x += x.x; acc.y += x.y; acc.z += x.z; acc.w += x.w;
    }

    __shared__ float4 sm4[NTHR];
    sm4[t] = acc;
    __syncthreads();
    if (t < 64) {
        float4 r = sm4[t];
        #pragma unroll
        for (int s = 1; s < 8; ++s) {
            const float4 a = sm4[t + 64 * s];
            r.x += a.x; r.y += a.y; r.z += a.z; r.w += a.w;
        }
        atomicAdd(&g_s[(4 * t + 0) * PAD], r.x);
        atomicAdd(&g_s[(4 * t + 1) * PAD], r.y);
        atomicAdd(&g_s[(4 * t + 2) * PAD], r.z);
        atomicAdd(&g_s[(4 * t + 3) * PAD], r.w);
    }
}

// ---------------------------------------------------------------------------
// k2: middle stage alone (64 blocks x 256 thr). Kernel boundary = sync.
// Block b: ksum cols jb..jb+3 = k_w^T s + N*k_b; then scatter
//   v += q_w[:,cols] * ksum_cols  and  c += q_b[cols] . ksum_cols
// via padded atomics. ~350KB total, L2-friendly, ~1us.
// ---------------------------------------------------------------------------
__global__ void __launch_bounds__(256, 4)
middle_kernel(const float* __restrict__ q_w,
              const float* __restrict__ q_b,
              const float* __restrict__ k_w,
              const float* __restrict__ k_b) {
    __shared__ float4 sm4[256];
    const int t  = threadIdx.x;
    const int jb = blockIdx.x * 4;

    const float  si = __ldcg(&g_s[t * PAD]);
    const float4 kw = *reinterpret_cast<const float4*>(
        k_w + (size_t)t * DIM + jb);
    sm4[t] = make_float4(si * kw.x, si * kw.y, si * kw.z, si * kw.w);
    __syncthreads();
    #pragma unroll
    for (int off = 128; off >= 1; off >>= 1) {
        if (t < off) {
            const float4 a = sm4[t], b = sm4[t + off];
            sm4[t] = make_float4(a.x + b.x, a.y + b.y, a.z + b.z, a.w + b.w);
        }
        __syncthreads();
    }
    if (t == 0) {
        const float4 kb = *reinterpret_cast<const float4*>(k_b + jb);
        float4 ks = sm4[0];
        ks.x += (float)N_TOTAL * kb.x;
        ks.y += (float)N_TOTAL * kb.y;
        ks.z += (float)N_TOTAL * kb.z;
        ks.w += (float)N_TOTAL * kb.w;
        sm4[0] = ks;
        const float4 qb = *reinterpret_cast<const float4*>(q_b + jb);
        atomicAdd(&g_c, qb.x * ks.x + qb.y * ks.y + qb.z * ks.z + qb.w * ks.w);
    }
    __syncthreads();
    const float4 ks = sm4[0];
    const float4 qw = *reinterpret_cast<const float4*>(
        q_w + (size_t)t * DIM + jb);
    atomicAdd(&g_vp[t * PAD],
              qw.x * ks.x + qw.y * ks.y + qw.z * ks.z + qw.w * ks.w);
}

// ---------------------------------------------------------------------------
// k3: out[i] = (combine[i] . v + c) / 16, combine = [mashup ; api].
// Pure stream in colsum's proven shape: 512 x 512, 2 rows/warp, 4
// independent float4 loads/thread, NO spin — v/c ready at kernel start.
// Block 0 zeroes g_s for the next graph replay (k3 never reads it).
// ---------------------------------------------------------------------------
__global__ void __launch_bounds__(NTHR, 4)
final_kernel(const float* __restrict__ mashup,
             const float* __restrict__ api,
             float* __restrict__ out) {
    __shared__ float vs[DIM];
    __shared__ float sc;
    const int t = threadIdx.x;

    if (blockIdx.x == 0) {                   // reset g_s for next replay
        #pragma unroll
        for (int m = 0; m < 16; ++m) g_s[t + NTHR * m] = 0.f;
    }

    if (t < DIM) vs[t] = __ldcg(&g_vp[t * PAD]);
    if (t == 0)  sc    = __ldcg(&g_c);
    __syncthreads();

    const int warp = t >> 5, lane = t & 31;
    const int row0 = (blockIdx.x * 16 + warp) * 2;   // never straddles 4096
    const float* src;
    int base;
    if (row0 < M_ROWS) { src = mashup; base = row0; }
    else               { src = api;    base = row0 - M_ROWS; }

    const float4* p0 = reinterpret_cast<const float4*>(src + (size_t)base * DIM);
    const float4* p1 = reinterpret_cast<const float4*>(src + (size_t)(base + 1) * DIM);
    const float4 a0 = p0[lane], a1 = p0[lane + 32];
    const float4 b0 = p1[lane], b1 = p1[lane + 32];

    const float4* vp = reinterpret_cast<const float4*>(vs);
    const float4 v0 = vp[lane], v1 = vp[lane + 32];

    float accA = a0.x * v0.x + a0.y * v0.y + a0.z * v0.z + a0.w * v0.w
               + a1.x * v1.x + a1.y * v1.y + a1.z * v1.z + a1.w * v1.w;
    float accB = b0.x * v0.x + b0.y * v0.y + b0.z * v0.z + b0.w * v0.w
               + b1.x * v1.x + b1.y * v1.y + b1.z * v1.z + b1.w * v1.w;

    #pragma unroll
    for (int off = 16; off > 0; off >>= 1) {
        accA += __shfl_xor_sync(0xFFFFFFFFu, accA, off);
        accB += __shfl_xor_sync(0xFFFFFFFFu, accB, off);
    }
    if (lane == 0) {
        out[row0]     = (accA + sc) * 0.0625f;       // 1/sqrt(256)
        out[row0 + 1] = (accB + sc) * 0.0625f;
    }
}

// ---------------------------------------------------------------------------
// Launch. Inputs (metadata order): mashup, api, new_api, q_w, q_b, k_w, k_b,
// embedding_dim (fixed 256, unused). THREE launches, zero device-side spins.
// ---------------------------------------------------------------------------
extern "C" void kernel_launch(void* const* d_in, const int* in_sizes, int n_in,
                              void* d_out, int out_size) {
    const float* mashup  = (const float*)d_in[0];
    const float* api     = (const float*)d_in[1];
    const float* new_api = (const float*)d_in[2];
    const float* q_w     = (const float*)d_in[3];
    const float* q_b     = (const float*)d_in[4];
    const float* k_w     = (const float*)d_in[5];
    const float* k_b     = (const float*)d_in[6];
    float* out = (float*)d_out;

    colsum_kernel<<<GRID, NTHR>>>(mashup, new_api);
    middle_kernel<<<DIM / 4, 256>>>(q_w, q_b, k_w, k_b);
    final_kernel <<<GRID, NTHR>>>(mashup, api, out);
}

// round 13
// speedup vs baseline: 1.5643x; 1.0135x over previous
#include <cuda_runtime.h>
#include <cuda_bf16.h>

#define N_TOTAL 16384
#define M_ROWS  4096
#define DIM     256
#define GRID    296          // exactly 2 blocks per SM (148 x 2), perfect balance
#define NTHR    512
#define NTHREADS (GRID * NTHR)          // 151552
#define TOTAL_F4 (N_TOTAL * (DIM / 4))  // 1048576 float4s in the combined matrix
#define SEG_F4   (M_ROWS * (DIM / 4))   // 262144 float4s in mashup
#define PAD     32           // 128B stride between atomic targets (own L2 line)

// Scratch (no allocation; zero at module load; self-rezeroing across replays)
__device__ float g_s [DIM * PAD];   // column sums (padded); zeroed by final blk0
__device__ float g_vp[DIM * PAD];   // v (padded atomic accum); zeroed by colsum blk0
__device__ float g_c;               // scalar; zeroed by colsum blk0

// ---------------------------------------------------------------------------
// k1: column sums of combine_new = [mashup ; new_api], LINEAR addressing.
// 296 x 512 @ 2 blocks/SM, 64-reg budget => ptxas can front-batch all 7
// independent float4 loads (MLP=7, ~114KB in flight per SM).
// Thread g = bid*512+t reads float4 indices p = g + k*151552, k=0..6
// (k=6 predicated: p<1048576). 151552 % 64 == 0 => column c4 = g&63 is
// constant per thread => single float4 accumulator. Warp reads 512B
// contiguous; block reads 8KB contiguous chunks.
// ---------------------------------------------------------------------------
__global__ void __launch_bounds__(NTHR, 2)
colsum_kernel(const float* __restrict__ mashup,
              const float* __restrict__ new_api) {
    const int t   = threadIdx.x;
    const int bid = blockIdx.x;
    const int g   = bid * NTHR + t;

    if (bid == 0) {                          // zero middle-stage accumulators
        #pragma unroll
        for (int m = 0; m < 16; ++m) g_vp[t + NTHR * m] = 0.f;
        if (t == 0) g_c = 0.f;
    }

    float4 acc = make_float4(0.f, 0.f, 0.f, 0.f);
    #pragma unroll
    for (int k = 0; k < 7; ++k) {
        const int p = g + k * NTHREADS;
        if (k < 6 || p < TOTAL_F4) {         // only k=6 needs the bound
            const float4* base = (p < SEG_F4)
                ? (reinterpret_cast<const float4*>(mashup) + p)
                : (reinterpret_cast<const float4*>(new_api) + (p - SEG_F4));
            const float4 x = *base;
            acc.x += x.x; acc.y += x.y; acc.z += x.z; acc.w += x.w;
        }
    }

    // block tree-reduce over the 8 sub-groups sharing each c4
    __shared__ float4 sm4[NTHR];
    sm4[t] = acc;
    __syncthreads();
    if (t < 64) {
        float4 r = sm4[t];
        #pragma unroll
        for (int s = 1; s < 8; ++s) {
            const float4 a = sm4[t + 64 * s];
            r.x += a.x; r.y += a.y; r.z += a.z; r.w += a.w;
        }
        atomicAdd(&g_s[(4 * t + 0) * PAD], r.x);
        atomicAdd(&g_s[(4 * t + 1) * PAD], r.y);
        atomicAdd(&g_s[(4 * t + 2) * PAD], r.z);
        atomicAdd(&g_s[(4 * t + 3) * PAD], r.w);
    }
}

// ---------------------------------------------------------------------------
// k2: middle stage (64 blocks x 256 thr). Kernel boundary = sync.
// Block b: ksum cols jb..jb+3 = k_w^T s + N*k_b; scatter
// v += q_w[:,cols]*ksum_cols and c += q_b[cols].ksum_cols via padded atomics.
// ---------------------------------------------------------------------------
__global__ void __launch_bounds__(256, 4)
middle_kernel(const float* __restrict__ q_w,
              const float* __restrict__ q_b,
              const float* __restrict__ k_w,
              const float* __restrict__ k_b) {
    __shared__ float4 sm4[256];
    const int t  = threadIdx.x;
    const int jb = blockIdx.x * 4;

    const float  si = __ldcg(&g_s[t * PAD]);
    const float4 kw = *reinterpret_cast<const float4*>(
        k_w + (size_t)t * DIM + jb);
    sm4[t] = make_float4(si * kw.x, si * kw.y, si * kw.z, si * kw.w);
    __syncthreads();
    #pragma unroll
    for (int off = 128; off >= 1; off >>= 1) {
        if (t < off) {
            const float4 a = sm4[t], b = sm4[t + off];
            sm4[t] = make_float4(a.x + b.x, a.y + b.y, a.z + b.z, a.w + b.w);
        }
        __syncthreads();
    }
    if (t == 0) {
        const float4 kb = *reinterpret_cast<const float4*>(k_b + jb);
        float4 ks = sm4[0];
        ks.x += (float)N_TOTAL * kb.x;
        ks.y += (float)N_TOTAL * kb.y;
        ks.z += (float)N_TOTAL * kb.z;
        ks.w += (float)N_TOTAL * kb.w;
        sm4[0] = ks;
        const float4 qb = *reinterpret_cast<const float4*>(q_b + jb);
        atomicAdd(&g_c, qb.x * ks.x + qb.y * ks.y + qb.z * ks.z + qb.w * ks.w);
    }
    __syncthreads();
    const float4 ks = sm4[0];
    const float4 qw = *reinterpret_cast<const float4*>(
        q_w + (size_t)t * DIM + jb);
    atomicAdd(&g_vp[t * PAD],
              qw.x * ks.x + qw.y * ks.y + qw.z * ks.z + qw.w * ks.w);
}

// ---------------------------------------------------------------------------
// k3: out[i] = (combine[i].v + c)/16, combine = [mashup ; api].
// 296 x 512 @ 2 blocks/SM, 64-reg budget. Warp w owns rows 4w..4w+3
// (predicated, whole-warp uniform; 4096 % 4 == 0 so no mashup/api straddle).
// 8 independent float4 loads per thread, front-batched. Block 0 zeroes g_s
// for the next graph replay.
// ---------------------------------------------------------------------------
__global__ void __launch_bounds__(NTHR, 2)
final_kernel(const float* __restrict__ mashup,
             const float* __restrict__ api,
             float* __restrict__ out) {
    __shared__ float vs[DIM];
    __shared__ float sc;
    const int t = threadIdx.x;

    if (blockIdx.x == 0) {                   // reset g_s for next replay
        #pragma unroll
        for (int m = 0; m < 16; ++m) g_s[t + NTHR * m] = 0.f;
    }

    if (t < DIM) vs[t] = __ldcg(&g_vp[t * PAD]);
    if (t == 0)  sc    = __ldcg(&g_c);
    __syncthreads();

    const int warp = t >> 5, lane = t & 31;
    const int row0 = (blockIdx.x * 16 + warp) * 4;   // 4 rows per warp
    if (row0 >= N_TOTAL) return;                      // warp-uniform

    const float* src;
    int base;
    if (row0 < M_ROWS) { src = mashup; base = row0; }
    else               { src = api;    base = row0 - M_ROWS; }

    const float4* vp = reinterpret_cast<const float4*>(vs);
    const float4 v0 = vp[lane], v1 = vp[lane + 32];

    // 8 independent loads (front-batched under the 64-reg budget)
    float4 x0[4], x1[4];
    #pragma unroll
    for (int r = 0; r < 4; ++r) {
        const float4* p = reinterpret_cast<const float4*>(
            src + (size_t)(base + r) * DIM);
        x0[r] = p[lane];
        x1[r] = p[lane + 32];
    }

    float acc[4];
    #pragma unroll
    for (int r = 0; r < 4; ++r) {
        acc[r] = x0[r].x * v0.x + x0[r].y * v0.y + x0[r].z * v0.z + x0[r].w * v0.w
               + x1[r].x * v1.x + x1[r].y * v1.y + x1[r].z * v1.z + x1[r].w * v1.w;
    }
    #pragma unroll
    for (int r = 0; r < 4; ++r) {
        float a = acc[r];
        #pragma unroll
        for (int off = 16; off > 0; off >>= 1)
            a += __shfl_xor_sync(0xFFFFFFFFu, a, off);
        if (lane == 0)
            out[row0 + r] = (a + sc) * 0.0625f;      // 1/sqrt(256)
    }
}

// ---------------------------------------------------------------------------
// Launch. Inputs (metadata order): mashup, api, new_api, q_w, q_b, k_w, k_b,
// embedding_dim (fixed 256, unused). THREE launches, zero device-side spins.
// ---------------------------------------------------------------------------
extern "C" void kernel_launch(void* const* d_in, const int* in_sizes, int n_in,
                              void* d_out, int out_size) {
    const float* mashup  = (const float*)d_in[0];
    const float* api     = (const float*)d_in[1];
    const float* new_api = (const float*)d_in[2];
    const float* q_w     = (const float*)d_in[3];
    const float* q_b     = (const float*)d_in[4];
    const float* k_w     = (const float*)d_in[5];
    const float* k_b     = (const float*)d_in[6];
    float* out = (float*)d_out;

    colsum_kernel<<<GRID, NTHR>>>(mashup, new_api);
    middle_kernel<<<DIM / 4, 256>>>(q_w, q_b, k_w, k_b);
    final_kernel <<<GRID, NTHR>>>(mashup, api, out);
}